// round 10
// baseline (speedup 1.0000x reference)
#include <cuda_runtime.h>
#include <cuda_fp16.h>
#include <math.h>
#include <stdint.h>

// Problem constants (fixed by the dataset)
#define NNODES 100000
#define EHALF  1600000
#define NEDGE  (2*EHALF)     // 3,200,000 symmetrized directed edges
#define NFEAT  512
#define NHID   256
#define NOUT   64
#define KORD   10            // Chebyshev order
#define SZNO   ((size_t)NNODES * NOUT)

// ---------------------------------------------------------------------------
// Scratch (static device globals; allocation APIs are forbidden)
// ---------------------------------------------------------------------------
__device__ float  g_xf[SZNO];                 // x fp32 (GEMM2 out, unscaled)
__device__ __half g_s0[SZNO];                 // s0 = dinv * x (fp16)
__device__ __half g_sT[(size_t)KORD * SZNO];  // s1..s10 (scaled Tx, fp16)
__device__ __half g_hidH[(size_t)NNODES * NHID];   // hidden fp16
__device__ __half g_W1h[(size_t)NHID * NFEAT];     // W1 fp16 [256,512]
__device__ __half g_W2h[(size_t)NOUT * NHID];      // W2 fp16 [64,256]
__device__ int   g_deg[NNODES];
__device__ float g_dinv[NNODES];              // deg^-1/2 (0 if deg==0)
__device__ float g_d2[NNODES];                // dinv^2
__device__ float g_sqd[NNODES];               // sqrt(deg) (0 if deg==0)
__device__ int   g_rowptr[NNODES + 1];
__device__ int   g_cursor[NNODES];
__device__ int   g_col[NEDGE];                // CSR columns only
__device__ float g_coe[KORD + 1];

// ---------------------------------------------------------------------------
// Base-target PTX helpers (mma.sync + ldmatrix + cp.async only)
// ---------------------------------------------------------------------------
__device__ __forceinline__ uint32_t smem_u32(const void* p) {
    uint32_t a;
    asm("{ .reg .u64 t; cvta.to.shared.u64 t, %1; cvt.u32.u64 %0, t; }" : "=r"(a) : "l"(p));
    return a;
}

#define LDSM4(R, addr) \
    asm volatile("ldmatrix.sync.aligned.m8n8.x4.shared.b16 {%0,%1,%2,%3}, [%4];" \
        : "=r"((R)[0]), "=r"((R)[1]), "=r"((R)[2]), "=r"((R)[3]) : "r"(addr))

#define MMA16816F16(C, A, b0, b1) \
    asm volatile("mma.sync.aligned.m16n8k16.row.col.f32.f16.f16.f32 " \
        "{%0,%1,%2,%3},{%4,%5,%6,%7},{%8,%9},{%0,%1,%2,%3};" \
        : "+f"((C)[0]), "+f"((C)[1]), "+f"((C)[2]), "+f"((C)[3]) \
        : "r"((A)[0]), "r"((A)[1]), "r"((A)[2]), "r"((A)[3]), "r"(b0), "r"(b1))

#define CP_ASYNC16(dst, src, zfill) \
    asm volatile("cp.async.cg.shared.global [%0], [%1], 16, %2;" \
        :: "r"((uint32_t)(dst)), "l"(src), "r"((uint32_t)(zfill)) : "memory")
#define CP_COMMIT() asm volatile("cp.async.commit_group;" ::: "memory")
#define CP_WAIT0()  asm volatile("cp.async.wait_group 0;" ::: "memory")
#define CP_WAIT1()  asm volatile("cp.async.wait_group 1;" ::: "memory")
#define CP_WAIT2()  asm volatile("cp.async.wait_group 2;" ::: "memory")

__device__ __forceinline__ uint32_t h2u(__half2 v) {
    return *(uint32_t*)&v;
}

// ---------------------------------------------------------------------------
// fp32 -> fp16 convert
// ---------------------------------------------------------------------------
__global__ void tohalf_kernel(const float* __restrict__ w, __half* __restrict__ h, int n) {
    int i = blockIdx.x * blockDim.x + threadIdx.x;
    if (i >= n) return;
    h[i] = __float2half(w[i]);
}

// ---------------------------------------------------------------------------
// GEMM1: hidden[N,256] = relu(feature[N,512] @ W1h[256,512]^T + b1), fp16 out.
// ---------------------------------------------------------------------------
__global__ __launch_bounds__(256, 2)
void gemm1_kernel(const float* __restrict__ Af32, const __half* __restrict__ Bh16,
                  const float* __restrict__ bias, __half* __restrict__ outHid,
                  int nrows) {
    constexpr int KT = NFEAT;              // 512
    constexpr int NCOL = NHID;             // 256
    constexpr int CH = KT / 64;            // 8
    constexpr uint32_t A32OFF = 0;         // 3 x 16384
    constexpr uint32_t A16OFF = 49152;     // 2 x 8192
    constexpr uint32_t BOFF2  = 65536;     // 3 x 16384

    extern __shared__ char smem[];
    const uint32_t sb = smem_u32(smem);
    const int tid = threadIdx.x, lane = tid & 31, wid = tid >> 5;
    const int warpM = wid >> 2, warpN = wid & 3;
    const int m0 = blockIdx.y * 64, n0 = blockIdx.x * 128;
    const int s = tid & 7,  rb = tid >> 3;
    const int s2 = tid & 15, rb2 = tid >> 4;

    float cacc[2][4][4];
#pragma unroll
    for (int mt = 0; mt < 2; mt++)
#pragma unroll
        for (int nt = 0; nt < 4; nt++)
#pragma unroll
            for (int q = 0; q < 4; q++) cacc[mt][nt][q] = 0.0f;

    auto ISSUE_A32 = [&](int c, int st) {
        const uint32_t aB = sb + A32OFF + (uint32_t)st * 16384u;
#pragma unroll
        for (int it = 0; it < 4; it++) {
            int r = rb2 + it * 16;
            int g = m0 + r;
            uint32_t zf = (g < nrows) ? 16u : 0u;
            const char* src = (const char*)(Af32 + (size_t)g * KT + c * 64 + s2 * 4);
            CP_ASYNC16(aB + (uint32_t)r * 256u + (uint32_t)s2 * 16u, src, zf);
        }
    };

    auto ISSUE_B = [&](int c, int st) {
        const uint32_t bB = sb + BOFF2 + (uint32_t)st * 16384u;
#pragma unroll
        for (int it = 0; it < 4; it++) {
            int r = rb + it * 32;
            uint32_t off = (uint32_t)r * 128u + (uint32_t)((s ^ (r & 7)) << 4);
            const char* src = (const char*)(Bh16 + (size_t)(n0 + r) * KT + c * 64 + s * 8);
            CP_ASYNC16(bB + off, src, 16);
        }
    };

    auto CONVERT = [&](int k) {
        const char* a32 = smem + A32OFF + (k % 3) * 16384;
        char* a16 = smem + A16OFF + (k & 1) * 8192;
        const int seg = s2 >> 1, sub = (s2 & 1) * 8;
#pragma unroll
        for (int it = 0; it < 4; it++) {
            int r = rb2 + it * 16;
            float4 v = *(const float4*)(a32 + r * 256 + s2 * 16);
            uint2 hv;
            hv.x = h2u(__floats2half2_rn(v.x, v.y));
            hv.y = h2u(__floats2half2_rn(v.z, v.w));
            *(uint2*)(a16 + r * 128 + ((seg ^ (r & 7)) << 4) + sub) = hv;
        }
    };

    auto COMPUTE = [&](int c) {
        const uint32_t aB = sb + A16OFF + (uint32_t)(c & 1) * 8192u;
        const uint32_t bB = sb + BOFF2 + (uint32_t)(c % 3) * 16384u;
        const int g = lane >> 3, r = lane & 7;
#pragma unroll
        for (int ks = 0; ks < 4; ks++) {
            uint32_t Afr[2][4], Bfr[2][4];
#pragma unroll
            for (int mt = 0; mt < 2; mt++) {
                int row = warpM * 32 + mt * 16 + (g & 1) * 8 + r;
                int seg = ks * 2 + (g >> 1);
                uint32_t off = (uint32_t)row * 128u + (uint32_t)((seg ^ (row & 7)) << 4);
                LDSM4(Afr[mt], aB + off);
            }
#pragma unroll
            for (int pt = 0; pt < 2; pt++) {
                int row = warpN * 32 + pt * 16 + (g >> 1) * 8 + r;
                int seg = ks * 2 + (g & 1);
                uint32_t off = (uint32_t)row * 128u + (uint32_t)((seg ^ (row & 7)) << 4);
                LDSM4(Bfr[pt], bB + off);
            }
#pragma unroll
            for (int mt = 0; mt < 2; mt++)
#pragma unroll
                for (int nt = 0; nt < 4; nt++) {
                    const uint32_t* b = &Bfr[nt >> 1][(nt & 1) * 2];
                    MMA16816F16(cacc[mt][nt], Afr[mt], b[0], b[1]);
                }
        }
    };

    ISSUE_A32(0, 0); CP_COMMIT();
    ISSUE_A32(1, 1); ISSUE_B(0, 0); CP_COMMIT();
    ISSUE_A32(2, 2); ISSUE_B(1, 1); CP_COMMIT();
    CP_WAIT2();
    __syncthreads();
    CONVERT(0);

    for (int c = 0; c < CH; c++) {
        CP_WAIT1();
        __syncthreads();
        if (c + 3 < CH) ISSUE_A32(c + 3, (c + 3) % 3);
        if (c + 2 < CH) ISSUE_B(c + 2, (c + 2) % 3);
        CP_COMMIT();
        if (c + 1 < CH) CONVERT(c + 1);
        COMPUTE(c);
    }

    const int qr = lane >> 2, qc = (lane & 3) * 2;
#pragma unroll
    for (int mt = 0; mt < 2; mt++) {
        int row0 = m0 + warpM * 32 + mt * 16 + qr;
#pragma unroll
        for (int nt = 0; nt < 4; nt++) {
            int col = n0 + warpN * 32 + nt * 8 + qc;
            float b0 = __ldg(bias + col), b1 = __ldg(bias + col + 1);
#pragma unroll
            for (int h = 0; h < 2; h++) {
                int row = row0 + h * 8;
                if (row >= nrows) continue;
                float x0 = fmaxf(cacc[mt][nt][h * 2 + 0] + b0, 0.f);
                float x1 = fmaxf(cacc[mt][nt][h * 2 + 1] + b1, 0.f);
                *(uint32_t*)(outHid + (size_t)row * NCOL + col) =
                    h2u(__floats2half2_rn(x0, x1));
            }
        }
    }
}

// ---------------------------------------------------------------------------
// GEMM2: x[N,64] = hidden[N,256] @ W2h[64,256]^T + b2; also s0 = dinv * x.
// ---------------------------------------------------------------------------
__global__ __launch_bounds__(256, 2)
void gemm2_kernel(const __half* __restrict__ Ah16, const __half* __restrict__ Bh16,
                  const float* __restrict__ bias, const float* __restrict__ dinv,
                  float* __restrict__ outF, __half* __restrict__ outS0, int nrows) {
    constexpr int KT = NHID;               // 256
    constexpr int NCOL = NOUT;             // 64
    constexpr int CH = KT / 64;            // 4
    constexpr uint32_t ASZ = 8192, BSZ = 8192;
    constexpr uint32_t BOFF2 = 3 * ASZ;

    extern __shared__ char smem[];
    const uint32_t sb = smem_u32(smem);
    const int tid = threadIdx.x, lane = tid & 31, wid = tid >> 5;
    const int warpM = wid >> 2, warpN = wid & 3;
    const int m0 = blockIdx.y * 64;
    const int s = tid & 7, rb = tid >> 3;

    float cacc[2][2][4];
#pragma unroll
    for (int mt = 0; mt < 2; mt++)
#pragma unroll
        for (int nt = 0; nt < 2; nt++)
#pragma unroll
            for (int q = 0; q < 4; q++) cacc[mt][nt][q] = 0.0f;

    auto ISSUE_A = [&](int c, int st) {
        const uint32_t aB = sb + (uint32_t)st * ASZ;
#pragma unroll
        for (int it = 0; it < 2; it++) {
            int r = rb + it * 32;
            int g = m0 + r;
            uint32_t zf = (g < nrows) ? 16u : 0u;
            uint32_t off = (uint32_t)r * 128u + (uint32_t)((s ^ (r & 7)) << 4);
            const char* src = (const char*)(Ah16 + (size_t)g * KT + c * 64 + s * 8);
            CP_ASYNC16(aB + off, src, zf);
        }
    };

    auto ISSUE_B = [&](int c, int st) {
        const uint32_t bB = sb + BOFF2 + (uint32_t)st * BSZ;
#pragma unroll
        for (int it = 0; it < 2; it++) {
            int r = rb + it * 32;
            uint32_t off = (uint32_t)r * 128u + (uint32_t)((s ^ (r & 7)) << 4);
            const char* src = (const char*)(Bh16 + (size_t)r * KT + c * 64 + s * 8);
            CP_ASYNC16(bB + off, src, 16);
        }
    };

    auto COMPUTE = [&](int c) {
        const uint32_t aB = sb + (uint32_t)(c % 3) * ASZ;
        const uint32_t bB = sb + BOFF2 + (uint32_t)(c % 3) * BSZ;
        const int g = lane >> 3, r = lane & 7;
#pragma unroll
        for (int ks = 0; ks < 4; ks++) {
            uint32_t Afr[2][4], Bfr[1][4];
#pragma unroll
            for (int mt = 0; mt < 2; mt++) {
                int row = warpM * 32 + mt * 16 + (g & 1) * 8 + r;
                int seg = ks * 2 + (g >> 1);
                uint32_t off = (uint32_t)row * 128u + (uint32_t)((seg ^ (row & 7)) << 4);
                LDSM4(Afr[mt], aB + off);
            }
            {
                int row = warpN * 16 + (g >> 1) * 8 + r;
                int seg = ks * 2 + (g & 1);
                uint32_t off = (uint32_t)row * 128u + (uint32_t)((seg ^ (row & 7)) << 4);
                LDSM4(Bfr[0], bB + off);
            }
#pragma unroll
            for (int mt = 0; mt < 2; mt++)
#pragma unroll
                for (int nt = 0; nt < 2; nt++) {
                    const uint32_t* b = &Bfr[0][nt * 2];
                    MMA16816F16(cacc[mt][nt], Afr[mt], b[0], b[1]);
                }
        }
    };

    ISSUE_A(0, 0); ISSUE_B(0, 0); CP_COMMIT();
    ISSUE_A(1, 1); ISSUE_B(1, 1); CP_COMMIT();

    for (int c = 0; c < CH; c++) {
        CP_WAIT1();
        __syncthreads();
        if (c + 2 < CH) { ISSUE_A(c + 2, (c + 2) % 3); ISSUE_B(c + 2, (c + 2) % 3); }
        CP_COMMIT();
        COMPUTE(c);
    }

    const int qr = lane >> 2, qc = (lane & 3) * 2;
#pragma unroll
    for (int mt = 0; mt < 2; mt++) {
        int row0 = m0 + warpM * 32 + mt * 16 + qr;
#pragma unroll
        for (int nt = 0; nt < 2; nt++) {
            int col = warpN * 16 + nt * 8 + qc;
            float b0 = __ldg(bias + col), b1 = __ldg(bias + col + 1);
#pragma unroll
            for (int h = 0; h < 2; h++) {
                int row = row0 + h * 8;
                if (row >= nrows) continue;
                float x0 = cacc[mt][nt][h * 2 + 0] + b0;
                float x1 = cacc[mt][nt][h * 2 + 1] + b1;
                *(float2*)(outF + (size_t)row * NCOL + col) = make_float2(x0, x1);
                float dv = __ldg(dinv + row);
                *(uint32_t*)(outS0 + (size_t)row * NCOL + col) =
                    h2u(__floats2half2_rn(dv * x0, dv * x1));
            }
        }
    }
}

// ---------------------------------------------------------------------------
// Chebyshev coefficients
// ---------------------------------------------------------------------------
__global__ void cheb_coeffs_kernel(const float* __restrict__ temp) {
    int i = threadIdx.x;
    if (i > KORD) return;
    const float PI = 3.14159265358979323846f;
    float s = 0.0f;
    for (int j = 0; j <= KORD; j++) {
        float t = fmaxf(temp[j], 0.0f);
        float theta = (KORD - j + 0.5f) * PI / (KORD + 1);
        s += t * cosf((float)i * theta);
    }
    float c = (2.0f / (KORD + 1)) * s;
    if (i == 0) c *= 0.5f;
    g_coe[i] = c;
}

// ---------------------------------------------------------------------------
// Graph preprocessing
// ---------------------------------------------------------------------------
__global__ void degree_kernel(const int* __restrict__ src, const int* __restrict__ dst,
                              int ehalf) {
    int e = blockIdx.x * blockDim.x + threadIdx.x;
    if (e >= ehalf) return;
    atomicAdd(&g_deg[src[e]], 1);
    atomicAdd(&g_deg[dst[e]], 1);
}

__global__ void dinv_kernel(int n) {
    int i = blockIdx.x * blockDim.x + threadIdx.x;
    if (i >= n) return;
    int d = g_deg[i];
    float dv = (d > 0) ? rsqrtf((float)d) : 0.0f;
    g_dinv[i] = dv;
    g_d2[i] = dv * dv;
    g_sqd[i] = (d > 0) ? sqrtf((float)d) : 0.0f;
}

__global__ void scan_kernel(int n) {
    __shared__ int sums[1024];
    int tid = threadIdx.x;
    int chunk = (n + 1023) / 1024;
    int start = tid * chunk;
    int end = min(start + chunk, n);
    int s = 0;
    for (int i = start; i < end; i++) s += g_deg[i];
    sums[tid] = s;
    __syncthreads();
    for (int off = 1; off < 1024; off <<= 1) {
        int v = 0;
        if (tid >= off) v = sums[tid - off];
        __syncthreads();
        if (tid >= off) sums[tid] += v;
        __syncthreads();
    }
    int prefix = (tid == 0) ? 0 : sums[tid - 1];
    for (int i = start; i < end; i++) {
        g_rowptr[i] = prefix;
        prefix += g_deg[i];
    }
    if (tid == 1023) g_rowptr[n] = prefix;
}

__global__ void build_csr_kernel(const int* __restrict__ src, const int* __restrict__ dst,
                                 int ehalf) {
    int e = blockIdx.x * blockDim.x + threadIdx.x;
    if (e >= ehalf) return;
    int s = src[e];
    int d = dst[e];
    int p1 = g_rowptr[s] + atomicAdd(&g_cursor[s], 1);
    g_col[p1] = d;
    int p2 = g_rowptr[d] + atomicAdd(&g_cursor[d], 1);
    g_col[p2] = s;
}

// ---------------------------------------------------------------------------
// Propagation over pre-scaled state s_i = dinv * Tx_i (unweighted gather).
// Grid-stride: grid sized to exactly fill the chip; each warp loops over
// node-groups (4 nodes/warp, 8 lanes/node, lane owns 8 feats).
// ---------------------------------------------------------------------------
__device__ __forceinline__ void csr_gather8u(const __half* __restrict__ v,
                                             int beg, int end, int lane,
                                             float* __restrict__ acc) {
    const int lane8 = lane & 7;
    const int grpBase = lane & 24;     // (lane>>3)*8
    for (int j = beg; __any_sync(0xffffffffu, j < end); j += 8) {
        int myc = -1;
        int idx = j + lane8;
        if (idx < end && j < end) myc = g_col[idx];
#pragma unroll
        for (int t = 0; t < 8; t++) {
            int c = __shfl_sync(0xffffffffu, myc, grpBase + t);
            if (c >= 0) {
                uint4 hv = *(const uint4*)(v + ((size_t)c << 6) + (lane8 << 3));
                const __half2* hp = (const __half2*)&hv;
                float2 f0 = __half22float2(hp[0]);
                float2 f1 = __half22float2(hp[1]);
                float2 f2 = __half22float2(hp[2]);
                float2 f3 = __half22float2(hp[3]);
                acc[0] += f0.x;  acc[1] += f0.y;
                acc[2] += f1.x;  acc[3] += f1.y;
                acc[4] += f2.x;  acc[5] += f2.y;
                acc[6] += f3.x;  acc[7] += f3.y;
            }
        }
    }
}

__device__ __forceinline__ uint4 pack_h8(const float* a) {
    uint4 r;
    *(__half2*)&r.x = __floats2half2_rn(a[0], a[1]);
    *(__half2*)&r.y = __floats2half2_rn(a[2], a[3]);
    *(__half2*)&r.z = __floats2half2_rn(a[4], a[5]);
    *(__half2*)&r.w = __floats2half2_rn(a[6], a[7]);
    return r;
}

// s1 = -d2 * gather(s0)
__global__ __launch_bounds__(256)
void prop_first_kernel(const __half* __restrict__ s0, __half* __restrict__ s1, int n) {
    const int lane = threadIdx.x & 31;
    const int gw0 = (blockIdx.x * blockDim.x + threadIdx.x) >> 5;
    const int totW = (gridDim.x * blockDim.x) >> 5;
    const int nwarps = (n + 3) >> 2;
    for (int gw = gw0; gw < nwarps; gw += totW) {
        int node = gw * 4 + (lane >> 3);
        bool ok = node < n;
        int beg = 0, end = 0;
        if (ok) { beg = g_rowptr[node]; end = g_rowptr[node + 1]; }
        float acc[8] = {0.f, 0.f, 0.f, 0.f, 0.f, 0.f, 0.f, 0.f};
        csr_gather8u(s0, beg, end, lane, acc);
        if (!ok) continue;
        float md2 = -g_d2[node];
#pragma unroll
        for (int q = 0; q < 8; q++) acc[q] *= md2;
        size_t fb = ((size_t)node << 6) + ((lane & 7) << 3);
        *(uint4*)(s1 + fb) = pack_h8(acc);
    }
}

// s_{i+1} = -2*d2*gather(s_i) - s_{i-1}
__global__ __launch_bounds__(256)
void prop_step_kernel(const __half* __restrict__ si, const __half* __restrict__ sim1,
                      __half* __restrict__ sip1, int n) {
    const int lane = threadIdx.x & 31;
    const int gw0 = (blockIdx.x * blockDim.x + threadIdx.x) >> 5;
    const int totW = (gridDim.x * blockDim.x) >> 5;
    const int nwarps = (n + 3) >> 2;
    for (int gw = gw0; gw < nwarps; gw += totW) {
        int node = gw * 4 + (lane >> 3);
        bool ok = node < n;
        int beg = 0, end = 0;
        if (ok) { beg = g_rowptr[node]; end = g_rowptr[node + 1]; }
        float acc[8] = {0.f, 0.f, 0.f, 0.f, 0.f, 0.f, 0.f, 0.f};
        csr_gather8u(si, beg, end, lane, acc);
        if (!ok) continue;
        float m2d2 = -2.0f * g_d2[node];
        size_t fb = ((size_t)node << 6) + ((lane & 7) << 3);
        uint4 t0v = *(const uint4*)(sim1 + fb);
        const __half2* t0p = (const __half2*)&t0v;
        float t2[8];
        {
            float2 a = __half22float2(t0p[0]), b = __half22float2(t0p[1]);
            float2 c = __half22float2(t0p[2]), d = __half22float2(t0p[3]);
            t2[0] = fmaf(m2d2, acc[0], -a.x);  t2[1] = fmaf(m2d2, acc[1], -a.y);
            t2[2] = fmaf(m2d2, acc[2], -b.x);  t2[3] = fmaf(m2d2, acc[3], -b.y);
            t2[4] = fmaf(m2d2, acc[4], -c.x);  t2[5] = fmaf(m2d2, acc[5], -c.y);
            t2[6] = fmaf(m2d2, acc[6], -d.x);  t2[7] = fmaf(m2d2, acc[7], -d.y);
        }
        *(uint4*)(sip1 + fb) = pack_h8(t2);
    }
}

// Last step fused with combine.
__global__ __launch_bounds__(256)
void prop_last_kernel(const __half* __restrict__ s9, const __half* __restrict__ s8,
                      const __half* __restrict__ sT, const float* __restrict__ xf,
                      float* __restrict__ out, int n) {
    const int lane = threadIdx.x & 31;
    const int gw0 = (blockIdx.x * blockDim.x + threadIdx.x) >> 5;
    const int totW = (gridDim.x * blockDim.x) >> 5;
    const int nwarps = (n + 3) >> 2;
    for (int gw = gw0; gw < nwarps; gw += totW) {
        int node = gw * 4 + (lane >> 3);
        bool ok = node < n;
        int beg = 0, end = 0;
        if (ok) { beg = g_rowptr[node]; end = g_rowptr[node + 1]; }
        float acc[8] = {0.f, 0.f, 0.f, 0.f, 0.f, 0.f, 0.f, 0.f};
        csr_gather8u(s9, beg, end, lane, acc);
        if (!ok) continue;
        size_t fb = ((size_t)node << 6) + ((lane & 7) << 3);

        float sqd = g_sqd[node];
        float c0 = g_coe[0];   // pre-halved
        float4 x0 = *(const float4*)(xf + fb);
        float4 x1 = *(const float4*)(xf + fb + 4);

        if (sqd == 0.0f) {     // isolated node: Tx_k = cos(k*pi/2) * x
            float cfb = c0 - g_coe[2] + g_coe[4] - g_coe[6] + g_coe[8] - g_coe[10];
            *(float4*)(out + fb) =
                make_float4(cfb * x0.x, cfb * x0.y, cfb * x0.z, cfb * x0.w);
            *(float4*)(out + fb + 4) =
                make_float4(cfb * x1.x, cfb * x1.y, cfb * x1.z, cfb * x1.w);
            continue;
        }

        float m2d2 = -2.0f * g_d2[node];
        float s10[8];
        {
            uint4 t0v = *(const uint4*)(s8 + fb);
            const __half2* t0p = (const __half2*)&t0v;
            float2 a = __half22float2(t0p[0]), b = __half22float2(t0p[1]);
            float2 c = __half22float2(t0p[2]), d = __half22float2(t0p[3]);
            s10[0] = fmaf(m2d2, acc[0], -a.x);  s10[1] = fmaf(m2d2, acc[1], -a.y);
            s10[2] = fmaf(m2d2, acc[2], -b.x);  s10[3] = fmaf(m2d2, acc[3], -b.y);
            s10[4] = fmaf(m2d2, acc[4], -c.x);  s10[5] = fmaf(m2d2, acc[5], -c.y);
            s10[6] = fmaf(m2d2, acc[6], -d.x);  s10[7] = fmaf(m2d2, acc[7], -d.y);
        }

        float res[8] = {0.f, 0.f, 0.f, 0.f, 0.f, 0.f, 0.f, 0.f};
#pragma unroll
        for (int k = 1; k <= KORD - 1; k++) {
            float ck = g_coe[k];
            uint4 v = *(const uint4*)(sT + (size_t)(k - 1) * SZNO + fb);
            const __half2* hp = (const __half2*)&v;
            float2 f0 = __half22float2(hp[0]);
            float2 f1 = __half22float2(hp[1]);
            float2 f2 = __half22float2(hp[2]);
            float2 f3 = __half22float2(hp[3]);
            res[0] = fmaf(ck, f0.x, res[0]);
            res[1] = fmaf(ck, f0.y, res[1]);
            res[2] = fmaf(ck, f1.x, res[2]);
            res[3] = fmaf(ck, f1.y, res[3]);
            res[4] = fmaf(ck, f2.x, res[4]);
            res[5] = fmaf(ck, f2.y, res[5]);
            res[6] = fmaf(ck, f3.x, res[6]);
            res[7] = fmaf(ck, f3.y, res[7]);
        }
        float cK = g_coe[KORD];
#pragma unroll
        for (int q = 0; q < 8; q++) res[q] = fmaf(cK, s10[q], res[q]);

        float o[8];
        o[0] = fmaf(sqd, res[0], c0 * x0.x);
        o[1] = fmaf(sqd, res[1], c0 * x0.y);
        o[2] = fmaf(sqd, res[2], c0 * x0.z);
        o[3] = fmaf(sqd, res[3], c0 * x0.w);
        o[4] = fmaf(sqd, res[4], c0 * x1.x);
        o[5] = fmaf(sqd, res[5], c0 * x1.y);
        o[6] = fmaf(sqd, res[6], c0 * x1.z);
        o[7] = fmaf(sqd, res[7], c0 * x1.w);
        *(float4*)(out + fb) = make_float4(o[0], o[1], o[2], o[3]);
        *(float4*)(out + fb + 4) = make_float4(o[4], o[5], o[6], o[7]);
    }
}

// ---------------------------------------------------------------------------
// Launch
// ---------------------------------------------------------------------------
extern "C" void kernel_launch(void* const* d_in, const int* in_sizes, int n_in,
                              void* d_out, int out_size) {
    const float* feature = (const float*)d_in[0];
    const float* W1      = (const float*)d_in[1];
    const float* b1      = (const float*)d_in[2];
    const float* W2      = (const float*)d_in[3];
    const float* b2      = (const float*)d_in[4];
    const float* temp    = (const float*)d_in[5];
    const int*   edge    = (const int*)d_in[6];

    const int n = NNODES;
    const int E = in_sizes[6] / 2;            // 3,200,000 directed
    const int Eh = E / 2;                     // 1,600,000 pairs
    const int* src = edge;
    const int* dst = edge + Eh;
    float* out = (float*)d_out;

    void *p_xf, *p_s0, *p_sT, *p_deg, *p_cursor, *p_hidH, *p_w1h, *p_w2h, *p_dinv;
    cudaGetSymbolAddress(&p_xf, g_xf);
    cudaGetSymbolAddress(&p_s0, g_s0);
    cudaGetSymbolAddress(&p_sT, g_sT);
    cudaGetSymbolAddress(&p_deg, g_deg);
    cudaGetSymbolAddress(&p_cursor, g_cursor);
    cudaGetSymbolAddress(&p_hidH, g_hidH);
    cudaGetSymbolAddress(&p_w1h, g_W1h);
    cudaGetSymbolAddress(&p_w2h, g_W2h);
    cudaGetSymbolAddress(&p_dinv, g_dinv);

    // 1. Chebyshev coefficients + weight conversion
    cheb_coeffs_kernel<<<1, 32>>>(temp);
    tohalf_kernel<<<(NHID * NFEAT + 255) / 256, 256>>>(W1, (__half*)p_w1h, NHID * NFEAT);
    tohalf_kernel<<<(NOUT * NHID + 255) / 256, 256>>>(W2, (__half*)p_w2h, NOUT * NHID);

    // 2. Graph preprocessing -> CSR (columns only) BEFORE GEMM2 (needs dinv)
    cudaMemsetAsync(p_deg, 0, n * sizeof(int), 0);
    cudaMemsetAsync(p_cursor, 0, n * sizeof(int), 0);
    degree_kernel<<<(Eh + 255) / 256, 256>>>(src, dst, Eh);
    dinv_kernel<<<(n + 255) / 256, 256>>>(n);
    scan_kernel<<<1, 1024>>>(n);
    build_csr_kernel<<<(Eh + 255) / 256, 256>>>(src, dst, Eh);

    // 3. MLP on mma.sync tensor cores
    {
        const int mblocks = (n + 63) / 64;                   // 1563
        const int smem1 = 3 * 16384 + 2 * 8192 + 3 * 16384;  // 114688
        const int smem2 = 3 * 8192 + 3 * 8192;               // 49152
        cudaFuncSetAttribute(gemm1_kernel,
                             cudaFuncAttributeMaxDynamicSharedMemorySize, smem1);
        cudaFuncSetAttribute(gemm2_kernel,
                             cudaFuncAttributeMaxDynamicSharedMemorySize, smem2);
        dim3 grid1(NHID / 128, mblocks);
        gemm1_kernel<<<grid1, 256, smem1>>>(feature, (const __half*)p_w1h, b1,
                                            (__half*)p_hidH, n);
        dim3 grid2(1, mblocks);
        gemm2_kernel<<<grid2, 256, smem2>>>((const __half*)p_hidH, (const __half*)p_w2h,
                                            b2, (const float*)p_dinv,
                                            (float*)p_xf, (__half*)p_s0, n);
    }

    // 4. Chebyshev propagation, grid sized to exactly fill the chip
    int sms = 148, blk1 = 8, blk2 = 8, blk3 = 8;
    cudaDeviceGetAttribute(&sms, cudaDevAttrMultiProcessorCount, 0);
    cudaOccupancyMaxActiveBlocksPerMultiprocessor(&blk1, prop_first_kernel, 256, 0);
    cudaOccupancyMaxActiveBlocksPerMultiprocessor(&blk2, prop_step_kernel, 256, 0);
    cudaOccupancyMaxActiveBlocksPerMultiprocessor(&blk3, prop_last_kernel, 256, 0);
    int nwarps = (n + 3) / 4;                      // 25000
    int maxb = (nwarps + 7) / 8;                   // 3125 (cap)
    int g1 = min(sms * blk1, maxb);
    int g2 = min(sms * blk2, maxb);
    int g3 = min(sms * blk3, maxb);

    __half* s0 = (__half*)p_s0;
    __half* sT = (__half*)p_sT;
    prop_first_kernel<<<g1, 256>>>(s0, sT, n);                            // s1
    prop_step_kernel<<<g2, 256>>>(sT, s0, sT + SZNO, n);                  // s2
    for (int i = 3; i <= KORD - 1; i++) {
        prop_step_kernel<<<g2, 256>>>(sT + (size_t)(i - 2) * SZNO,
                                      sT + (size_t)(i - 3) * SZNO,
                                      sT + (size_t)(i - 1) * SZNO, n);
    }
    prop_last_kernel<<<g3, 256>>>(sT + (size_t)(KORD - 2) * SZNO,
                                  sT + (size_t)(KORD - 3) * SZNO,
                                  sT, (const float*)p_xf, out, n);

    (void)n_in; (void)out_size;
}

// round 11
// speedup vs baseline: 1.1516x; 1.1516x over previous
#include <cuda_runtime.h>
#include <cuda_fp16.h>
#include <math.h>
#include <stdint.h>

// Problem constants (fixed by the dataset)
#define NNODES 100000
#define EHALF  1600000
#define NEDGE  (2*EHALF)     // 3,200,000 symmetrized directed edges
#define NFEAT  512
#define NHID   256
#define NOUT   64
#define KORD   10            // Chebyshev order
#define SZNO   ((size_t)NNODES * NOUT)

// ---------------------------------------------------------------------------
// Scratch (static device globals; allocation APIs are forbidden)
// ---------------------------------------------------------------------------
__device__ float  g_xf[SZNO];                 // x fp32 (GEMM2 out, unscaled)
__device__ __half g_s0[SZNO];                 // s0 = dinv * x (fp16)
__device__ __half g_sT[(size_t)KORD * SZNO];  // s1..s10 (scaled Tx, fp16)
__device__ __half g_hidH[(size_t)NNODES * NHID];   // hidden fp16
__device__ __half g_W1h[(size_t)NHID * NFEAT];     // W1 fp16 [256,512]
__device__ __half g_W2h[(size_t)NOUT * NHID];      // W2 fp16 [64,256]
__device__ int   g_deg[NNODES];
__device__ float g_dinv[NNODES];              // deg^-1/2 (0 if deg==0)
__device__ float g_d2[NNODES];                // dinv^2
__device__ float g_sqd[NNODES];               // sqrt(deg) (0 if deg==0)
__device__ int   g_rowptr[NNODES + 1];
__device__ int   g_cursor[NNODES];
__device__ int   g_col[NEDGE];                // CSR columns only
__device__ float g_coe[KORD + 1];

// ---------------------------------------------------------------------------
// Base-target PTX helpers (mma.sync + ldmatrix + cp.async only)
// ---------------------------------------------------------------------------
__device__ __forceinline__ uint32_t smem_u32(const void* p) {
    uint32_t a;
    asm("{ .reg .u64 t; cvta.to.shared.u64 t, %1; cvt.u32.u64 %0, t; }" : "=r"(a) : "l"(p));
    return a;
}

#define LDSM4(R, addr) \
    asm volatile("ldmatrix.sync.aligned.m8n8.x4.shared.b16 {%0,%1,%2,%3}, [%4];" \
        : "=r"((R)[0]), "=r"((R)[1]), "=r"((R)[2]), "=r"((R)[3]) : "r"(addr))

#define MMA16816F16(C, A, b0, b1) \
    asm volatile("mma.sync.aligned.m16n8k16.row.col.f32.f16.f16.f32 " \
        "{%0,%1,%2,%3},{%4,%5,%6,%7},{%8,%9},{%0,%1,%2,%3};" \
        : "+f"((C)[0]), "+f"((C)[1]), "+f"((C)[2]), "+f"((C)[3]) \
        : "r"((A)[0]), "r"((A)[1]), "r"((A)[2]), "r"((A)[3]), "r"(b0), "r"(b1))

#define CP_ASYNC16(dst, src, zfill) \
    asm volatile("cp.async.cg.shared.global [%0], [%1], 16, %2;" \
        :: "r"((uint32_t)(dst)), "l"(src), "r"((uint32_t)(zfill)) : "memory")
#define CP_COMMIT() asm volatile("cp.async.commit_group;" ::: "memory")
#define CP_WAIT0()  asm volatile("cp.async.wait_group 0;" ::: "memory")
#define CP_WAIT1()  asm volatile("cp.async.wait_group 1;" ::: "memory")
#define CP_WAIT2()  asm volatile("cp.async.wait_group 2;" ::: "memory")

__device__ __forceinline__ uint32_t h2u(__half2 v) {
    return *(uint32_t*)&v;
}

// ---------------------------------------------------------------------------
// fp32 -> fp16 convert
// ---------------------------------------------------------------------------
__global__ void tohalf_kernel(const float* __restrict__ w, __half* __restrict__ h, int n) {
    int i = blockIdx.x * blockDim.x + threadIdx.x;
    if (i >= n) return;
    h[i] = __float2half(w[i]);
}

// ---------------------------------------------------------------------------
// GEMM1: hidden[N,256] = relu(feature[N,512] @ W1h[256,512]^T + b1), fp16 out.
// ---------------------------------------------------------------------------
__global__ __launch_bounds__(256, 2)
void gemm1_kernel(const float* __restrict__ Af32, const __half* __restrict__ Bh16,
                  const float* __restrict__ bias, __half* __restrict__ outHid,
                  int nrows) {
    constexpr int KT = NFEAT;              // 512
    constexpr int NCOL = NHID;             // 256
    constexpr int CH = KT / 64;            // 8
    constexpr uint32_t A32OFF = 0;         // 3 x 16384
    constexpr uint32_t A16OFF = 49152;     // 2 x 8192
    constexpr uint32_t BOFF2  = 65536;     // 3 x 16384

    extern __shared__ char smem[];
    const uint32_t sb = smem_u32(smem);
    const int tid = threadIdx.x, lane = tid & 31, wid = tid >> 5;
    const int warpM = wid >> 2, warpN = wid & 3;
    const int m0 = blockIdx.y * 64, n0 = blockIdx.x * 128;
    const int s = tid & 7,  rb = tid >> 3;
    const int s2 = tid & 15, rb2 = tid >> 4;

    float cacc[2][4][4];
#pragma unroll
    for (int mt = 0; mt < 2; mt++)
#pragma unroll
        for (int nt = 0; nt < 4; nt++)
#pragma unroll
            for (int q = 0; q < 4; q++) cacc[mt][nt][q] = 0.0f;

    auto ISSUE_A32 = [&](int c, int st) {
        const uint32_t aB = sb + A32OFF + (uint32_t)st * 16384u;
#pragma unroll
        for (int it = 0; it < 4; it++) {
            int r = rb2 + it * 16;
            int g = m0 + r;
            uint32_t zf = (g < nrows) ? 16u : 0u;
            const char* src = (const char*)(Af32 + (size_t)g * KT + c * 64 + s2 * 4);
            CP_ASYNC16(aB + (uint32_t)r * 256u + (uint32_t)s2 * 16u, src, zf);
        }
    };

    auto ISSUE_B = [&](int c, int st) {
        const uint32_t bB = sb + BOFF2 + (uint32_t)st * 16384u;
#pragma unroll
        for (int it = 0; it < 4; it++) {
            int r = rb + it * 32;
            uint32_t off = (uint32_t)r * 128u + (uint32_t)((s ^ (r & 7)) << 4);
            const char* src = (const char*)(Bh16 + (size_t)(n0 + r) * KT + c * 64 + s * 8);
            CP_ASYNC16(bB + off, src, 16);
        }
    };

    auto CONVERT = [&](int k) {
        const char* a32 = smem + A32OFF + (k % 3) * 16384;
        char* a16 = smem + A16OFF + (k & 1) * 8192;
        const int seg = s2 >> 1, sub = (s2 & 1) * 8;
#pragma unroll
        for (int it = 0; it < 4; it++) {
            int r = rb2 + it * 16;
            float4 v = *(const float4*)(a32 + r * 256 + s2 * 16);
            uint2 hv;
            hv.x = h2u(__floats2half2_rn(v.x, v.y));
            hv.y = h2u(__floats2half2_rn(v.z, v.w));
            *(uint2*)(a16 + r * 128 + ((seg ^ (r & 7)) << 4) + sub) = hv;
        }
    };

    auto COMPUTE = [&](int c) {
        const uint32_t aB = sb + A16OFF + (uint32_t)(c & 1) * 8192u;
        const uint32_t bB = sb + BOFF2 + (uint32_t)(c % 3) * 16384u;
        const int g = lane >> 3, r = lane & 7;
#pragma unroll
        for (int ks = 0; ks < 4; ks++) {
            uint32_t Afr[2][4], Bfr[2][4];
#pragma unroll
            for (int mt = 0; mt < 2; mt++) {
                int row = warpM * 32 + mt * 16 + (g & 1) * 8 + r;
                int seg = ks * 2 + (g >> 1);
                uint32_t off = (uint32_t)row * 128u + (uint32_t)((seg ^ (row & 7)) << 4);
                LDSM4(Afr[mt], aB + off);
            }
#pragma unroll
            for (int pt = 0; pt < 2; pt++) {
                int row = warpN * 32 + pt * 16 + (g >> 1) * 8 + r;
                int seg = ks * 2 + (g & 1);
                uint32_t off = (uint32_t)row * 128u + (uint32_t)((seg ^ (row & 7)) << 4);
                LDSM4(Bfr[pt], bB + off);
            }
#pragma unroll
            for (int mt = 0; mt < 2; mt++)
#pragma unroll
                for (int nt = 0; nt < 4; nt++) {
                    const uint32_t* b = &Bfr[nt >> 1][(nt & 1) * 2];
                    MMA16816F16(cacc[mt][nt], Afr[mt], b[0], b[1]);
                }
        }
    };

    ISSUE_A32(0, 0); CP_COMMIT();
    ISSUE_A32(1, 1); ISSUE_B(0, 0); CP_COMMIT();
    ISSUE_A32(2, 2); ISSUE_B(1, 1); CP_COMMIT();
    CP_WAIT2();
    __syncthreads();
    CONVERT(0);

    for (int c = 0; c < CH; c++) {
        CP_WAIT1();
        __syncthreads();
        if (c + 3 < CH) ISSUE_A32(c + 3, (c + 3) % 3);
        if (c + 2 < CH) ISSUE_B(c + 2, (c + 2) % 3);
        CP_COMMIT();
        if (c + 1 < CH) CONVERT(c + 1);
        COMPUTE(c);
    }

    const int qr = lane >> 2, qc = (lane & 3) * 2;
#pragma unroll
    for (int mt = 0; mt < 2; mt++) {
        int row0 = m0 + warpM * 32 + mt * 16 + qr;
#pragma unroll
        for (int nt = 0; nt < 4; nt++) {
            int col = n0 + warpN * 32 + nt * 8 + qc;
            float b0 = __ldg(bias + col), b1 = __ldg(bias + col + 1);
#pragma unroll
            for (int h = 0; h < 2; h++) {
                int row = row0 + h * 8;
                if (row >= nrows) continue;
                float x0 = fmaxf(cacc[mt][nt][h * 2 + 0] + b0, 0.f);
                float x1 = fmaxf(cacc[mt][nt][h * 2 + 1] + b1, 0.f);
                *(uint32_t*)(outHid + (size_t)row * NCOL + col) =
                    h2u(__floats2half2_rn(x0, x1));
            }
        }
    }
}

// ---------------------------------------------------------------------------
// GEMM2: x[N,64] = hidden[N,256] @ W2h[64,256]^T + b2; also s0 = dinv * x.
// ---------------------------------------------------------------------------
__global__ __launch_bounds__(256, 2)
void gemm2_kernel(const __half* __restrict__ Ah16, const __half* __restrict__ Bh16,
                  const float* __restrict__ bias, const float* __restrict__ dinv,
                  float* __restrict__ outF, __half* __restrict__ outS0, int nrows) {
    constexpr int KT = NHID;               // 256
    constexpr int NCOL = NOUT;             // 64
    constexpr int CH = KT / 64;            // 4
    constexpr uint32_t ASZ = 8192, BSZ = 8192;
    constexpr uint32_t BOFF2 = 3 * ASZ;

    extern __shared__ char smem[];
    const uint32_t sb = smem_u32(smem);
    const int tid = threadIdx.x, lane = tid & 31, wid = tid >> 5;
    const int warpM = wid >> 2, warpN = wid & 3;
    const int m0 = blockIdx.y * 64;
    const int s = tid & 7, rb = tid >> 3;

    float cacc[2][2][4];
#pragma unroll
    for (int mt = 0; mt < 2; mt++)
#pragma unroll
        for (int nt = 0; nt < 2; nt++)
#pragma unroll
            for (int q = 0; q < 4; q++) cacc[mt][nt][q] = 0.0f;

    auto ISSUE_A = [&](int c, int st) {
        const uint32_t aB = sb + (uint32_t)st * ASZ;
#pragma unroll
        for (int it = 0; it < 2; it++) {
            int r = rb + it * 32;
            int g = m0 + r;
            uint32_t zf = (g < nrows) ? 16u : 0u;
            uint32_t off = (uint32_t)r * 128u + (uint32_t)((s ^ (r & 7)) << 4);
            const char* src = (const char*)(Ah16 + (size_t)g * KT + c * 64 + s * 8);
            CP_ASYNC16(aB + off, src, zf);
        }
    };

    auto ISSUE_B = [&](int c, int st) {
        const uint32_t bB = sb + BOFF2 + (uint32_t)st * BSZ;
#pragma unroll
        for (int it = 0; it < 2; it++) {
            int r = rb + it * 32;
            uint32_t off = (uint32_t)r * 128u + (uint32_t)((s ^ (r & 7)) << 4);
            const char* src = (const char*)(Bh16 + (size_t)r * KT + c * 64 + s * 8);
            CP_ASYNC16(bB + off, src, 16);
        }
    };

    auto COMPUTE = [&](int c) {
        const uint32_t aB = sb + (uint32_t)(c % 3) * ASZ;
        const uint32_t bB = sb + BOFF2 + (uint32_t)(c % 3) * BSZ;
        const int g = lane >> 3, r = lane & 7;
#pragma unroll
        for (int ks = 0; ks < 4; ks++) {
            uint32_t Afr[2][4], Bfr[1][4];
#pragma unroll
            for (int mt = 0; mt < 2; mt++) {
                int row = warpM * 32 + mt * 16 + (g & 1) * 8 + r;
                int seg = ks * 2 + (g >> 1);
                uint32_t off = (uint32_t)row * 128u + (uint32_t)((seg ^ (row & 7)) << 4);
                LDSM4(Afr[mt], aB + off);
            }
            {
                int row = warpN * 16 + (g >> 1) * 8 + r;
                int seg = ks * 2 + (g & 1);
                uint32_t off = (uint32_t)row * 128u + (uint32_t)((seg ^ (row & 7)) << 4);
                LDSM4(Bfr[0], bB + off);
            }
#pragma unroll
            for (int mt = 0; mt < 2; mt++)
#pragma unroll
                for (int nt = 0; nt < 2; nt++) {
                    const uint32_t* b = &Bfr[0][nt * 2];
                    MMA16816F16(cacc[mt][nt], Afr[mt], b[0], b[1]);
                }
        }
    };

    ISSUE_A(0, 0); ISSUE_B(0, 0); CP_COMMIT();
    ISSUE_A(1, 1); ISSUE_B(1, 1); CP_COMMIT();

    for (int c = 0; c < CH; c++) {
        CP_WAIT1();
        __syncthreads();
        if (c + 2 < CH) { ISSUE_A(c + 2, (c + 2) % 3); ISSUE_B(c + 2, (c + 2) % 3); }
        CP_COMMIT();
        COMPUTE(c);
    }

    const int qr = lane >> 2, qc = (lane & 3) * 2;
#pragma unroll
    for (int mt = 0; mt < 2; mt++) {
        int row0 = m0 + warpM * 32 + mt * 16 + qr;
#pragma unroll
        for (int nt = 0; nt < 2; nt++) {
            int col = warpN * 16 + nt * 8 + qc;
            float b0 = __ldg(bias + col), b1 = __ldg(bias + col + 1);
#pragma unroll
            for (int h = 0; h < 2; h++) {
                int row = row0 + h * 8;
                if (row >= nrows) continue;
                float x0 = cacc[mt][nt][h * 2 + 0] + b0;
                float x1 = cacc[mt][nt][h * 2 + 1] + b1;
                *(float2*)(outF + (size_t)row * NCOL + col) = make_float2(x0, x1);
                float dv = __ldg(dinv + row);
                *(uint32_t*)(outS0 + (size_t)row * NCOL + col) =
                    h2u(__floats2half2_rn(dv * x0, dv * x1));
            }
        }
    }
}

// ---------------------------------------------------------------------------
// Chebyshev coefficients
// ---------------------------------------------------------------------------
__global__ void cheb_coeffs_kernel(const float* __restrict__ temp) {
    int i = threadIdx.x;
    if (i > KORD) return;
    const float PI = 3.14159265358979323846f;
    float s = 0.0f;
    for (int j = 0; j <= KORD; j++) {
        float t = fmaxf(temp[j], 0.0f);
        float theta = (KORD - j + 0.5f) * PI / (KORD + 1);
        s += t * cosf((float)i * theta);
    }
    float c = (2.0f / (KORD + 1)) * s;
    if (i == 0) c *= 0.5f;
    g_coe[i] = c;
}

// ---------------------------------------------------------------------------
// Graph preprocessing
// ---------------------------------------------------------------------------
__global__ void degree_kernel(const int* __restrict__ src, const int* __restrict__ dst,
                              int ehalf) {
    int e = blockIdx.x * blockDim.x + threadIdx.x;
    if (e >= ehalf) return;
    atomicAdd(&g_deg[src[e]], 1);
    atomicAdd(&g_deg[dst[e]], 1);
}

__global__ void dinv_kernel(int n) {
    int i = blockIdx.x * blockDim.x + threadIdx.x;
    if (i >= n) return;
    int d = g_deg[i];
    float dv = (d > 0) ? rsqrtf((float)d) : 0.0f;
    g_dinv[i] = dv;
    g_d2[i] = dv * dv;
    g_sqd[i] = (d > 0) ? sqrtf((float)d) : 0.0f;
}

__global__ void scan_kernel(int n) {
    __shared__ int sums[1024];
    int tid = threadIdx.x;
    int chunk = (n + 1023) / 1024;
    int start = tid * chunk;
    int end = min(start + chunk, n);
    int s = 0;
    for (int i = start; i < end; i++) s += g_deg[i];
    sums[tid] = s;
    __syncthreads();
    for (int off = 1; off < 1024; off <<= 1) {
        int v = 0;
        if (tid >= off) v = sums[tid - off];
        __syncthreads();
        if (tid >= off) sums[tid] += v;
        __syncthreads();
    }
    int prefix = (tid == 0) ? 0 : sums[tid - 1];
    for (int i = start; i < end; i++) {
        g_rowptr[i] = prefix;
        prefix += g_deg[i];
    }
    if (tid == 1023) g_rowptr[n] = prefix;
}

__global__ void build_csr_kernel(const int* __restrict__ src, const int* __restrict__ dst,
                                 int ehalf) {
    int e = blockIdx.x * blockDim.x + threadIdx.x;
    if (e >= ehalf) return;
    int s = src[e];
    int d = dst[e];
    int p1 = g_rowptr[s] + atomicAdd(&g_cursor[s], 1);
    g_col[p1] = d;
    int p2 = g_rowptr[d] + atomicAdd(&g_cursor[d], 1);
    g_col[p2] = s;
}

// ---------------------------------------------------------------------------
// Propagation over pre-scaled state s_i = dinv * Tx_i (unweighted gather).
// 4 nodes/warp, 8 lanes/node, lane owns 8 feats (uint4 of fp16).
// Next-batch neighbor indices are software-prefetched so the index LDG
// overlaps the 8 gather loads of the current batch.
// ---------------------------------------------------------------------------
__device__ __forceinline__ void csr_gather8u(const __half* __restrict__ v,
                                             int beg, int end, int lane,
                                             float* __restrict__ acc) {
    const int lane8 = lane & 7;
    const int grpBase = lane & 24;     // (lane>>3)*8
    int idx = beg + lane8;
    int myc = (idx < end) ? g_col[idx] : -1;
    for (int j = beg; __any_sync(0xffffffffu, j < end); j += 8) {
        // prefetch next batch's index while current batch computes
        int nidx = idx + 8;
        int nxt = (nidx < end) ? g_col[nidx] : -1;
#pragma unroll
        for (int t = 0; t < 8; t++) {
            int c = __shfl_sync(0xffffffffu, myc, grpBase + t);
            if (c >= 0) {
                uint4 hv = *(const uint4*)(v + ((size_t)c << 6) + (lane8 << 3));
                const __half2* hp = (const __half2*)&hv;
                float2 f0 = __half22float2(hp[0]);
                float2 f1 = __half22float2(hp[1]);
                float2 f2 = __half22float2(hp[2]);
                float2 f3 = __half22float2(hp[3]);
                acc[0] += f0.x;  acc[1] += f0.y;
                acc[2] += f1.x;  acc[3] += f1.y;
                acc[4] += f2.x;  acc[5] += f2.y;
                acc[6] += f3.x;  acc[7] += f3.y;
            }
        }
        myc = nxt;
        idx = nidx;
    }
}

__device__ __forceinline__ uint4 pack_h8(const float* a) {
    uint4 r;
    *(__half2*)&r.x = __floats2half2_rn(a[0], a[1]);
    *(__half2*)&r.y = __floats2half2_rn(a[2], a[3]);
    *(__half2*)&r.z = __floats2half2_rn(a[4], a[5]);
    *(__half2*)&r.w = __floats2half2_rn(a[6], a[7]);
    return r;
}

// s1 = -d2 * gather(s0)
__global__ __launch_bounds__(256)
void prop_first_kernel(const __half* __restrict__ s0, __half* __restrict__ s1, int n) {
    int gw = (blockIdx.x * blockDim.x + threadIdx.x) >> 5;
    int lane = threadIdx.x & 31;
    int node = gw * 4 + (lane >> 3);
    bool ok = node < n;
    int beg = 0, end = 0;
    if (ok) { beg = g_rowptr[node]; end = g_rowptr[node + 1]; }
    float acc[8] = {0.f, 0.f, 0.f, 0.f, 0.f, 0.f, 0.f, 0.f};
    csr_gather8u(s0, beg, end, lane, acc);
    if (!ok) return;
    float md2 = -g_d2[node];
#pragma unroll
    for (int q = 0; q < 8; q++) acc[q] *= md2;
    size_t fb = ((size_t)node << 6) + ((lane & 7) << 3);
    *(uint4*)(s1 + fb) = pack_h8(acc);
}

// s_{i+1} = -2*d2*gather(s_i) - s_{i-1}
__global__ __launch_bounds__(256)
void prop_step_kernel(const __half* __restrict__ si, const __half* __restrict__ sim1,
                      __half* __restrict__ sip1, int n) {
    int gw = (blockIdx.x * blockDim.x + threadIdx.x) >> 5;
    int lane = threadIdx.x & 31;
    int node = gw * 4 + (lane >> 3);
    bool ok = node < n;
    int beg = 0, end = 0;
    if (ok) { beg = g_rowptr[node]; end = g_rowptr[node + 1]; }
    float acc[8] = {0.f, 0.f, 0.f, 0.f, 0.f, 0.f, 0.f, 0.f};
    csr_gather8u(si, beg, end, lane, acc);
    if (!ok) return;
    float m2d2 = -2.0f * g_d2[node];
    size_t fb = ((size_t)node << 6) + ((lane & 7) << 3);
    uint4 t0v = *(const uint4*)(sim1 + fb);
    const __half2* t0p = (const __half2*)&t0v;
    float t2[8];
    {
        float2 a = __half22float2(t0p[0]), b = __half22float2(t0p[1]);
        float2 c = __half22float2(t0p[2]), d = __half22float2(t0p[3]);
        t2[0] = fmaf(m2d2, acc[0], -a.x);  t2[1] = fmaf(m2d2, acc[1], -a.y);
        t2[2] = fmaf(m2d2, acc[2], -b.x);  t2[3] = fmaf(m2d2, acc[3], -b.y);
        t2[4] = fmaf(m2d2, acc[4], -c.x);  t2[5] = fmaf(m2d2, acc[5], -c.y);
        t2[6] = fmaf(m2d2, acc[6], -d.x);  t2[7] = fmaf(m2d2, acc[7], -d.y);
    }
    *(uint4*)(sip1 + fb) = pack_h8(t2);
}

// Last step fused with combine:
// s10 = -2*d2*gather(s9) - s8 (regs)
// deg>0: out = c0*x + sqd_r * (sum_{k=1..9} coe_k s_k + coe_10 s10)
// deg=0: out = (c0 - coe2 + coe4 - coe6 + coe8 - coe10) * x
__global__ __launch_bounds__(256)
void prop_last_kernel(const __half* __restrict__ s9, const __half* __restrict__ s8,
                      const __half* __restrict__ sT, const float* __restrict__ xf,
                      float* __restrict__ out, int n) {
    int gw = (blockIdx.x * blockDim.x + threadIdx.x) >> 5;
    int lane = threadIdx.x & 31;
    int node = gw * 4 + (lane >> 3);
    bool ok = node < n;
    int beg = 0, end = 0;
    if (ok) { beg = g_rowptr[node]; end = g_rowptr[node + 1]; }
    float acc[8] = {0.f, 0.f, 0.f, 0.f, 0.f, 0.f, 0.f, 0.f};
    csr_gather8u(s9, beg, end, lane, acc);
    if (!ok) return;
    size_t fb = ((size_t)node << 6) + ((lane & 7) << 3);

    float sqd = g_sqd[node];
    float c0 = g_coe[0];   // pre-halved
    float4 x0 = *(const float4*)(xf + fb);
    float4 x1 = *(const float4*)(xf + fb + 4);

    if (sqd == 0.0f) {     // isolated node: Tx_k = cos(k*pi/2) * x exactly
        float cfb = c0 - g_coe[2] + g_coe[4] - g_coe[6] + g_coe[8] - g_coe[10];
        *(float4*)(out + fb) = make_float4(cfb * x0.x, cfb * x0.y, cfb * x0.z, cfb * x0.w);
        *(float4*)(out + fb + 4) = make_float4(cfb * x1.x, cfb * x1.y, cfb * x1.z, cfb * x1.w);
        return;
    }

    float m2d2 = -2.0f * g_d2[node];
    float s10[8];
    {
        uint4 t0v = *(const uint4*)(s8 + fb);
        const __half2* t0p = (const __half2*)&t0v;
        float2 a = __half22float2(t0p[0]), b = __half22float2(t0p[1]);
        float2 c = __half22float2(t0p[2]), d = __half22float2(t0p[3]);
        s10[0] = fmaf(m2d2, acc[0], -a.x);  s10[1] = fmaf(m2d2, acc[1], -a.y);
        s10[2] = fmaf(m2d2, acc[2], -b.x);  s10[3] = fmaf(m2d2, acc[3], -b.y);
        s10[4] = fmaf(m2d2, acc[4], -c.x);  s10[5] = fmaf(m2d2, acc[5], -c.y);
        s10[6] = fmaf(m2d2, acc[6], -d.x);  s10[7] = fmaf(m2d2, acc[7], -d.y);
    }

    float res[8] = {0.f, 0.f, 0.f, 0.f, 0.f, 0.f, 0.f, 0.f};
#pragma unroll
    for (int k = 1; k <= KORD - 1; k++) {
        float ck = g_coe[k];
        uint4 v = *(const uint4*)(sT + (size_t)(k - 1) * SZNO + fb);
        const __half2* hp = (const __half2*)&v;
        float2 f0 = __half22float2(hp[0]);
        float2 f1 = __half22float2(hp[1]);
        float2 f2 = __half22float2(hp[2]);
        float2 f3 = __half22float2(hp[3]);
        res[0] = fmaf(ck, f0.x, res[0]);
        res[1] = fmaf(ck, f0.y, res[1]);
        res[2] = fmaf(ck, f1.x, res[2]);
        res[3] = fmaf(ck, f1.y, res[3]);
        res[4] = fmaf(ck, f2.x, res[4]);
        res[5] = fmaf(ck, f2.y, res[5]);
        res[6] = fmaf(ck, f3.x, res[6]);
        res[7] = fmaf(ck, f3.y, res[7]);
    }
    float cK = g_coe[KORD];
#pragma unroll
    for (int q = 0; q < 8; q++) res[q] = fmaf(cK, s10[q], res[q]);

    float o[8];
    o[0] = fmaf(sqd, res[0], c0 * x0.x);
    o[1] = fmaf(sqd, res[1], c0 * x0.y);
    o[2] = fmaf(sqd, res[2], c0 * x0.z);
    o[3] = fmaf(sqd, res[3], c0 * x0.w);
    o[4] = fmaf(sqd, res[4], c0 * x1.x);
    o[5] = fmaf(sqd, res[5], c0 * x1.y);
    o[6] = fmaf(sqd, res[6], c0 * x1.z);
    o[7] = fmaf(sqd, res[7], c0 * x1.w);
    *(float4*)(out + fb) = make_float4(o[0], o[1], o[2], o[3]);
    *(float4*)(out + fb + 4) = make_float4(o[4], o[5], o[6], o[7]);
}

// ---------------------------------------------------------------------------
// Launch
// ---------------------------------------------------------------------------
extern "C" void kernel_launch(void* const* d_in, const int* in_sizes, int n_in,
                              void* d_out, int out_size) {
    const float* feature = (const float*)d_in[0];
    const float* W1      = (const float*)d_in[1];
    const float* b1      = (const float*)d_in[2];
    const float* W2      = (const float*)d_in[3];
    const float* b2      = (const float*)d_in[4];
    const float* temp    = (const float*)d_in[5];
    const int*   edge    = (const int*)d_in[6];

    const int n = NNODES;
    const int E = in_sizes[6] / 2;            // 3,200,000 directed
    const int Eh = E / 2;                     // 1,600,000 pairs
    const int* src = edge;
    const int* dst = edge + Eh;
    float* out = (float*)d_out;

    void *p_xf, *p_s0, *p_sT, *p_deg, *p_cursor, *p_hidH, *p_w1h, *p_w2h, *p_dinv;
    cudaGetSymbolAddress(&p_xf, g_xf);
    cudaGetSymbolAddress(&p_s0, g_s0);
    cudaGetSymbolAddress(&p_sT, g_sT);
    cudaGetSymbolAddress(&p_deg, g_deg);
    cudaGetSymbolAddress(&p_cursor, g_cursor);
    cudaGetSymbolAddress(&p_hidH, g_hidH);
    cudaGetSymbolAddress(&p_w1h, g_W1h);
    cudaGetSymbolAddress(&p_w2h, g_W2h);
    cudaGetSymbolAddress(&p_dinv, g_dinv);

    // 1. Chebyshev coefficients + weight conversion
    cheb_coeffs_kernel<<<1, 32>>>(temp);
    tohalf_kernel<<<(NHID * NFEAT + 255) / 256, 256>>>(W1, (__half*)p_w1h, NHID * NFEAT);
    tohalf_kernel<<<(NOUT * NHID + 255) / 256, 256>>>(W2, (__half*)p_w2h, NOUT * NHID);

    // 2. Graph preprocessing -> CSR (columns only) BEFORE GEMM2 (needs dinv)
    cudaMemsetAsync(p_deg, 0, n * sizeof(int), 0);
    cudaMemsetAsync(p_cursor, 0, n * sizeof(int), 0);
    degree_kernel<<<(Eh + 255) / 256, 256>>>(src, dst, Eh);
    dinv_kernel<<<(n + 255) / 256, 256>>>(n);
    scan_kernel<<<1, 1024>>>(n);
    build_csr_kernel<<<(Eh + 255) / 256, 256>>>(src, dst, Eh);

    // 3. MLP on mma.sync tensor cores
    {
        const int mblocks = (n + 63) / 64;                   // 1563
        const int smem1 = 3 * 16384 + 2 * 8192 + 3 * 16384;  // 114688
        const int smem2 = 3 * 8192 + 3 * 8192;               // 49152
        cudaFuncSetAttribute(gemm1_kernel,
                             cudaFuncAttributeMaxDynamicSharedMemorySize, smem1);
        cudaFuncSetAttribute(gemm2_kernel,
                             cudaFuncAttributeMaxDynamicSharedMemorySize, smem2);
        dim3 grid1(NHID / 128, mblocks);
        gemm1_kernel<<<grid1, 256, smem1>>>(feature, (const __half*)p_w1h, b1,
                                            (__half*)p_hidH, n);
        dim3 grid2(1, mblocks);
        gemm2_kernel<<<grid2, 256, smem2>>>((const __half*)p_hidH, (const __half*)p_w2h,
                                            b2, (const float*)p_dinv,
                                            (float*)p_xf, (__half*)p_s0, n);
    }

    // 4. Chebyshev propagation (many small blocks — HW scheduler balances)
    int nwarps = (n + 3) / 4;                      // 25000
    int pblocks = (nwarps + 7) / 8;                // 3125
    __half* s0 = (__half*)p_s0;
    __half* sT = (__half*)p_sT;
    prop_first_kernel<<<pblocks, 256>>>(s0, sT, n);                       // s1
    prop_step_kernel<<<pblocks, 256>>>(sT, s0, sT + SZNO, n);             // s2
    for (int i = 3; i <= KORD - 1; i++) {
        prop_step_kernel<<<pblocks, 256>>>(sT + (size_t)(i - 2) * SZNO,
                                           sT + (size_t)(i - 3) * SZNO,
                                           sT + (size_t)(i - 1) * SZNO, n);
    }
    prop_last_kernel<<<pblocks, 256>>>(sT + (size_t)(KORD - 2) * SZNO,
                                       sT + (size_t)(KORD - 3) * SZNO,
                                       sT, (const float*)p_xf, out, n);

    (void)n_in; (void)out_size;
}